// round 8
// baseline (speedup 1.0000x reference)
#include <cuda_runtime.h>
#include <math.h>

#define NN 256
#define TT 1000
#define NO_ 10
#define NS_ 10
#define DD 20      // NO_ + NS_
#define HH 64
#define GG 192     // 3*HH

typedef unsigned long long ull;

// Scratch (no allocations allowed): hidden states
__device__ float g_hs[(size_t)NN * TT * HH];   // 65.5 MB
__device__ double g_acc;
__device__ unsigned int g_done;

// ---- packed f32x2 helpers (Blackwell sm_103a) ------------------------------
__device__ __forceinline__ ull pack2(float lo, float hi) {
    ull r; asm("mov.b64 %0,{%1,%2};" : "=l"(r) : "f"(lo), "f"(hi)); return r;
}
__device__ __forceinline__ float2 unpack2(ull v) {
    float lo, hi; asm("mov.b64 {%0,%1},%2;" : "=f"(lo), "=f"(hi) : "l"(v));
    return make_float2(lo, hi);
}
__device__ __forceinline__ ull fma2(ull a, ull b, ull c) {
    ull d; asm("fma.rn.f32x2 %0,%1,%2,%3;" : "=l"(d) : "l"(a), "l"(b), "l"(c)); return d;
}
__device__ __forceinline__ ull add2(ull a, ull b) {
    ull d; asm("add.rn.f32x2 %0,%1,%2;" : "=l"(d) : "l"(a), "l"(b)); return d;
}
__device__ __forceinline__ float tanh_fast(float x) {
    float y; asm("tanh.approx.f32 %0,%1;" : "=f"(y) : "f"(x)); return y;
}
__device__ __forceinline__ float sigmoid_fast(float x) {
    return fmaf(0.5f, tanh_fast(0.5f * x), 0.5f);
}

// ---------------------------------------------------------------------------
// GRU scan: 256 blocks x 128 threads (1 sample/block, 2 blocks/SM).
//   threads 0..63  (consumers): unit k owns gate columns {k, 64+k, 128+k};
//     all three h-projections + gates are THREAD-LOCAL -> no projection
//     exchange, ONE __syncthreads per step, double-buffered sh_h.
//   threads 64..127 (producers): compute xp(t+1) = x(t+1)@Wi + bi into a
//     depth-2 shared ring one step ahead; prefetch x(t+4) from DRAM.
// ---------------------------------------------------------------------------
__global__ void __launch_bounds__(128, 2) gru_scan_kernel(
    const float* __restrict__ Yi, const float* __restrict__ Xh,
    const float* __restrict__ Wi, const float* __restrict__ Wh,
    const float* __restrict__ bi, const float* __restrict__ bh)
{
    __shared__ __align__(16) float sh_h[2][HH];
    __shared__ __align__(16) float sh_x[2][DD];
    __shared__ __align__(16) float sh_xp[2][GG];

    const int tid = threadIdx.x;
    const int n = blockIdx.x;
    if (n == 0 && tid == 0) { g_acc = 0.0; g_done = 0u; }

    const bool cons = (tid < HH);
    const int k = tid;          // consumer unit id (valid when cons)
    const int p = tid - HH;     // producer id 0..63 (valid when !cons)

    // ---- consumer state: Wh columns k, 64+k, 128+k packed as f32x2 --------
    ull whr[HH / 2], whz[HH / 2], whn[HH / 2];
    float bhr = 0.f, bhz = 0.f, bhn = 0.f;
    float hprev = 0.0f;
    if (cons) {
#pragma unroll
        for (int q = 0; q < HH / 2; q++) {
            whr[q] = pack2(Wh[(2 * q) * GG + k],            Wh[(2 * q + 1) * GG + k]);
            whz[q] = pack2(Wh[(2 * q) * GG + HH + k],       Wh[(2 * q + 1) * GG + HH + k]);
            whn[q] = pack2(Wh[(2 * q) * GG + 2 * HH + k],   Wh[(2 * q + 1) * GG + 2 * HH + k]);
        }
        bhr = bh[k]; bhz = bh[HH + k]; bhn = bh[2 * HH + k];
        sh_h[0][k] = 0.0f;
    }

    // ---- producer state: Wi columns p, 64+p, 128+p packed as f32x2 --------
    ull wir[DD / 2], wiz[DD / 2], win[DD / 2];
    float bir = 0.f, biz = 0.f, bin = 0.f;
    const float* src = 0;       // x loader (producers 0..19)
    float xa = 0.0f, xb = 0.0f;
    if (!cons) {
#pragma unroll
        for (int q = 0; q < DD / 2; q++) {
            wir[q] = pack2(Wi[(2 * q) * GG + p],          Wi[(2 * q + 1) * GG + p]);
            wiz[q] = pack2(Wi[(2 * q) * GG + HH + p],     Wi[(2 * q + 1) * GG + HH + p]);
            win[q] = pack2(Wi[(2 * q) * GG + 2 * HH + p], Wi[(2 * q + 1) * GG + 2 * HH + p]);
        }
        bir = bi[p]; biz = bi[HH + p]; bin = bi[2 * HH + p];
        if (p < DD) {
            src = (p < NO_) ? (Yi + (size_t)n * TT * NO_ + p)
                            : (Xh + (size_t)n * TT * NS_ + (p - NO_));
            sh_x[0][p] = src[0];                 // x(0)
            sh_x[1][p] = src[NS_];               // x(1)
            xa = src[2 * NS_];                   // x(2)
            xb = src[3 * NS_];                   // x(3)
        }
    }
    __syncthreads();

    // producers: xp(0) into ring slot 0
    if (!cons) {
        const ull* x2 = (const ull*)sh_x[0];
        ull cr = pack2(bir, 0.0f), cz = pack2(biz, 0.0f), cn = pack2(bin, 0.0f);
#pragma unroll
        for (int q = 0; q < DD / 2; q++) {
            cr = fma2(x2[q], wir[q], cr);
            cz = fma2(x2[q], wiz[q], cz);
            cn = fma2(x2[q], win[q], cn);
        }
        float2 f;
        f = unpack2(cr); sh_xp[0][p]          = f.x + f.y;
        f = unpack2(cz); sh_xp[0][HH + p]     = f.x + f.y;
        f = unpack2(cn); sh_xp[0][2 * HH + p] = f.x + f.y;
    }
    __syncthreads();

    float* hs = g_hs + (size_t)n * TT * HH;

    for (int t = 0; t < TT; t++) {
        const int slot = t & 1;
        if (cons) {
            // --- three h-projections, all local (96 FFMA2, 6 chains) ---
            const ulonglong2* h4 = (const ulonglong2*)sh_h[slot];
            ull ar0 = 0ull, ar1 = 0ull, az0 = 0ull, az1 = 0ull, an0 = 0ull, an1 = 0ull;
#pragma unroll
            for (int q = 0; q < HH / 4; q++) {
                const ulonglong2 hv = h4[q];
                ar0 = fma2(hv.x, whr[2 * q], ar0); ar1 = fma2(hv.y, whr[2 * q + 1], ar1);
                az0 = fma2(hv.x, whz[2 * q], az0); az1 = fma2(hv.y, whz[2 * q + 1], az1);
                an0 = fma2(hv.x, whn[2 * q], an0); an1 = fma2(hv.y, whn[2 * q + 1], an1);
            }
            float2 f;
            f = unpack2(add2(ar0, ar1)); const float ar = f.x + f.y + bhr;
            f = unpack2(add2(az0, az1)); const float az = f.x + f.y + bhz;
            f = unpack2(add2(an0, an1)); const float an = f.x + f.y + bhn;

            const float xr = sh_xp[slot][k];
            const float xz = sh_xp[slot][HH + k];
            const float xn = sh_xp[slot][2 * HH + k];

            const float r = sigmoid_fast(xr + ar);
            const float z = sigmoid_fast(xz + az);
            const float nn = tanh_fast(fmaf(r, an, xn));
            const float hnew = fmaf(z, hprev - nn, nn);   // (1-z)n + z h
            hprev = hnew;
            sh_h[slot ^ 1][k] = hnew;
            hs[(size_t)t * HH + k] = hnew;
        } else {
            // --- produce xp(t+1) into the other ring slot ---
            if (t + 1 < TT) {
                const ull* x2 = (const ull*)sh_x[slot ^ 1];
                ull cr = pack2(bir, 0.0f), cz = pack2(biz, 0.0f), cn = pack2(bin, 0.0f);
#pragma unroll
                for (int q = 0; q < DD / 2; q++) {
                    cr = fma2(x2[q], wir[q], cr);
                    cz = fma2(x2[q], wiz[q], cz);
                    cn = fma2(x2[q], win[q], cn);
                }
                float2 f;
                f = unpack2(cr); sh_xp[slot ^ 1][p]          = f.x + f.y;
                f = unpack2(cz); sh_xp[slot ^ 1][HH + p]     = f.x + f.y;
                f = unpack2(cn); sh_xp[slot ^ 1][2 * HH + p] = f.x + f.y;
            }
            if (p < DD) {
                if (t + 2 < TT) sh_x[slot][p] = xa;        // x(t+2) -> slot (t+2)&1
                xa = xb;
                if (t + 4 < TT) xb = src[(size_t)(t + 4) * NS_];
            }
        }
        __syncthreads();
    }
}

// ---------------------------------------------------------------------------
// Likelihood: one thread per (n,t); FFMA2 heads, packed Cholesky in registers.
// Last block writes the final scalar (no separate finalize launch).
// ---------------------------------------------------------------------------
__global__ void __launch_bounds__(256) lik_kernel(
    const float* __restrict__ Yi, const float* __restrict__ Cw,
    const float* __restrict__ Hm, const float* __restrict__ mu_w,
    const float* __restrict__ W_mu, const float* __restrict__ b_mu,
    const float* __restrict__ W_var, const float* __restrict__ b_var,
    float* __restrict__ out)
{
    __shared__ ull sWm2[(HH / 2) * NS_];
    __shared__ ull sWv2[(HH / 2) * NS_];
    __shared__ float sH[NO_ * NS_], sbm[NS_], sbv[NS_], smw[NO_];
    __shared__ double wsum[8];

    const int tid = threadIdx.x;
    for (int i = tid; i < (HH / 2) * NS_; i += 256) {
        const int p = i / NS_, j = i - p * NS_;
        sWm2[i] = pack2(W_mu[(2 * p) * NS_ + j],  W_mu[(2 * p + 1) * NS_ + j]);
        sWv2[i] = pack2(W_var[(2 * p) * NS_ + j], W_var[(2 * p + 1) * NS_ + j]);
    }
    if (tid < NO_ * NS_) sH[tid] = Hm[tid];
    if (tid < NS_) { sbm[tid] = b_mu[tid]; sbv[tid] = b_var[tid]; }
    if (tid < NO_) smw[tid] = mu_w[tid];
    __syncthreads();

    const int idx = blockIdx.x * 256 + tid;      // grid is exact: NN*TT/256
    const int n = idx / TT;

    // heads: mu = h@W_mu + b_mu ; vr = h@W_var + b_var   (packed f32x2)
    ull mu2[NS_], vr2[NS_];
#pragma unroll
    for (int j = 0; j < NS_; j++) { mu2[j] = 0ull; vr2[j] = 0ull; }

    const ulonglong2* h4 = (const ulonglong2*)(g_hs + (size_t)idx * HH);
#pragma unroll
    for (int q = 0; q < HH / 4; q++) {
        const ulonglong2 hv = h4[q];
        const int p0 = 2 * q;
#pragma unroll
        for (int j = 0; j < NS_; j++) {
            mu2[j] = fma2(hv.x, sWm2[p0 * NS_ + j], mu2[j]);
            vr2[j] = fma2(hv.x, sWv2[p0 * NS_ + j], vr2[j]);
        }
#pragma unroll
        for (int j = 0; j < NS_; j++) {
            mu2[j] = fma2(hv.y, sWm2[(p0 + 1) * NS_ + j], mu2[j]);
            vr2[j] = fma2(hv.y, sWv2[(p0 + 1) * NS_ + j], vr2[j]);
        }
    }

    float mu[NS_], var[NS_];
#pragma unroll
    for (int j = 0; j < NS_; j++) {
        const float2 m = unpack2(mu2[j]);
        mu[j] = sbm[j] + m.x + m.y;
        const float2 v = unpack2(vr2[j]);
        const float x = sbv[j] + v.x + v.y;
        var[j] = (x > 15.0f) ? x : __logf(1.0f + __expf(x));   // softplus
    }

    // residual e = y - (H mu + mu_w)
    float e[NO_];
#pragma unroll
    for (int i = 0; i < NO_; i++) {
        float m = smw[i];
#pragma unroll
        for (int j = 0; j < NS_; j++) m = fmaf(sH[i * NS_ + j], mu[j], m);
        e[i] = Yi[(size_t)idx * NO_ + i] - m;
    }

    // A = H diag(var) H^T + Cw, packed lower triangle
    float A[NO_ * (NO_ + 1) / 2];
    const float* cw = Cw + (size_t)n * NO_ * NO_;
#pragma unroll
    for (int i = 0; i < NO_; i++)
#pragma unroll
        for (int kk = 0; kk <= i; kk++)
            A[i * (i + 1) / 2 + kk] = cw[i * NO_ + kk];
#pragma unroll
    for (int j = 0; j < NS_; j++) {
        const float vj = var[j];
        float hj[NO_];
#pragma unroll
        for (int i = 0; i < NO_; i++) hj[i] = sH[i * NS_ + j];
#pragma unroll
        for (int i = 0; i < NO_; i++) {
            const float hv = hj[i] * vj;
#pragma unroll
            for (int kk = 0; kk <= i; kk++)
                A[i * (i + 1) / 2 + kk] = fmaf(hv, hj[kk], A[i * (i + 1) / 2 + kk]);
        }
    }

    // in-place packed Cholesky; logdet = sum log(s_i) since Lii^2 = s_i
    float rdi[NO_];
    float logdet = 0.0f;
#pragma unroll
    for (int i = 0; i < NO_; i++) {
#pragma unroll
        for (int kk = 0; kk < i; kk++) {
            float s = A[i * (i + 1) / 2 + kk];
#pragma unroll
            for (int j2 = 0; j2 < NO_; j2++)
                if (j2 < kk)
                    s -= A[i * (i + 1) / 2 + j2] * A[kk * (kk + 1) / 2 + j2];
            A[i * (i + 1) / 2 + kk] = s * rdi[kk];
        }
        float s = A[i * (i + 1) / 2 + i];
#pragma unroll
        for (int j2 = 0; j2 < NO_; j2++)
            if (j2 < i) {
                const float l = A[i * (i + 1) / 2 + j2];
                s -= l * l;
            }
        rdi[i] = rsqrtf(s);
        logdet += __logf(s);
    }

    // forward solve z = L^{-1} e ; quad = |z|^2
    float quad = 0.0f;
    float zv[NO_];
#pragma unroll
    for (int i = 0; i < NO_; i++) {
        float s = e[i];
#pragma unroll
        for (int j2 = 0; j2 < NO_; j2++)
            if (j2 < i) s -= A[i * (i + 1) / 2 + j2] * zv[j2];
        zv[i] = s * rdi[i];
        quad = fmaf(zv[i], zv[i], quad);
    }

    double local = (double)(logdet + quad);

    // block reduction -> one atomicAdd; last block finalizes
    for (int off = 16; off > 0; off >>= 1)
        local += __shfl_down_sync(0xffffffffu, local, off);
    if ((tid & 31) == 0) wsum[tid >> 5] = local;
    __syncthreads();
    if (tid == 0) {
        double s = 0.0;
#pragma unroll
        for (int w = 0; w < 8; w++) s += wsum[w];
        atomicAdd(&g_acc, s);
        __threadfence();
        const unsigned int d = atomicAdd(&g_done, 1u);
        if (d == gridDim.x - 1) {
            __threadfence();
            const double LOG2PI = 1.8378770664093453;
            const double acc = *((volatile double*)&g_acc);
            out[0] = (float)(-0.5 * LOG2PI - 0.5 * acc / ((double)NN * TT * NO_));
        }
    }
}

extern "C" void kernel_launch(void* const* d_in, const int* in_sizes, int n_in,
                              void* d_out, int out_size)
{
    const float* Yi    = (const float*)d_in[0];
    const float* Xh    = (const float*)d_in[1];
    const float* Cw    = (const float*)d_in[2];
    const float* Hm    = (const float*)d_in[3];
    const float* mu_w  = (const float*)d_in[4];
    const float* Wi    = (const float*)d_in[5];
    const float* Wh    = (const float*)d_in[6];
    const float* bi    = (const float*)d_in[7];
    const float* bh    = (const float*)d_in[8];
    const float* W_mu  = (const float*)d_in[9];
    const float* b_mu  = (const float*)d_in[10];
    const float* W_var = (const float*)d_in[11];
    const float* b_var = (const float*)d_in[12];
    float* out = (float*)d_out;

    gru_scan_kernel<<<NN, 128>>>(Yi, Xh, Wi, Wh, bi, bh);
    lik_kernel<<<NN * TT / 256, 256>>>(Yi, Cw, Hm, mu_w, W_mu, b_mu, W_var, b_var, out);
}

// round 10
// speedup vs baseline: 2.3529x; 2.3529x over previous
#include <cuda_runtime.h>
#include <math.h>

#define NN 256
#define TT 1000
#define NO_ 10
#define NS_ 10
#define DD 20      // NO_ + NS_
#define HH 64
#define GG 192     // 3*HH

typedef unsigned long long ull;

// Scratch (no allocations allowed): hidden states
__device__ float g_hs[(size_t)NN * TT * HH];   // 65.5 MB
__device__ double g_acc;
__device__ unsigned int g_done;

// ---- packed f32x2 helpers (Blackwell sm_103a) ------------------------------
__device__ __forceinline__ ull pack2(float lo, float hi) {
    ull r; asm("mov.b64 %0,{%1,%2};" : "=l"(r) : "f"(lo), "f"(hi)); return r;
}
__device__ __forceinline__ float2 unpack2(ull v) {
    float lo, hi; asm("mov.b64 {%0,%1},%2;" : "=f"(lo), "=f"(hi) : "l"(v));
    return make_float2(lo, hi);
}
__device__ __forceinline__ ull fma2(ull a, ull b, ull c) {
    ull d; asm("fma.rn.f32x2 %0,%1,%2,%3;" : "=l"(d) : "l"(a), "l"(b), "l"(c)); return d;
}
__device__ __forceinline__ ull add2(ull a, ull b) {
    ull d; asm("add.rn.f32x2 %0,%1,%2;" : "=l"(d) : "l"(a), "l"(b)); return d;
}
__device__ __forceinline__ float tanh_fast(float x) {
    float y; asm("tanh.approx.f32 %0,%1;" : "=f"(y) : "f"(x)); return y;
}
__device__ __forceinline__ float sigmoid_fast(float x) {
    return fmaf(0.5f, tanh_fast(0.5f * x), 0.5f);
}

#define BAR_SYNC_1()   asm volatile("bar.sync 1, 192;" ::: "memory")
#define BAR_ARRIVE_1() asm volatile("bar.arrive 1, 192;" ::: "memory")

// ---------------------------------------------------------------------------
// Fused GRU scan: 256 blocks x 256 threads (1 sample/block, 2 blocks/SM).
//   threads 0..191  (proj): ONE Wh gate column each (32 ull regs); thread
//     k<64 additionally runs the gate math for hidden unit k.
//   threads 192..255 (producers): THREE Wi columns each (30 ull regs),
//     compute xp(t+1) into a depth-2 shared ring, one step ahead; producers
//     0..19 also stream x from DRAM with a 2-step prefetch pipeline.
//   CRITICAL: both roles store their weights in the SAME ull w[32] array so
//     ptxas allocates one 64-register block (R8's spill bug fix).
//   One __syncthreads per step + split named barrier (only gate warps wait).
// ---------------------------------------------------------------------------
__global__ void __launch_bounds__(256, 2) gru_scan_kernel(
    const float* __restrict__ Yi, const float* __restrict__ Xh,
    const float* __restrict__ Wi, const float* __restrict__ Wh,
    const float* __restrict__ bi, const float* __restrict__ bh)
{
    __shared__ __align__(16) float sh_h[2][HH];   // double-buffered hidden state
    __shared__ __align__(16) float sh_x[2][DD];   // raw input ring
    __shared__ __align__(16) float sh_xp[2][GG];  // input-projection ring
    __shared__ float sh_g[GG];                    // xp + hproj (all gate pre-acts)
    __shared__ float sh_hn[HH];                   // hproj only, n-gate columns

    const int tid = threadIdx.x;
    const int n = blockIdx.x;
    if (n == 0 && tid == 0) { g_acc = 0.0; g_done = 0u; }

    const bool proj = (tid < GG);
    const int k = tid;          // proj column id (valid when proj)
    const int p = tid - GG;     // producer id 0..63 (valid when !proj)

    // ---- unified weight register file (64 regs for BOTH roles) ------------
    ull w[32];
    float b0 = 0.f, b1 = 0.f, b2 = 0.f;
    float hprev = 0.0f;
    if (proj) {
#pragma unroll
        for (int q = 0; q < HH / 2; q++)
            w[q] = pack2(Wh[(2 * q) * GG + k], Wh[(2 * q + 1) * GG + k]);
        b0 = bh[k];
        if (k < HH) sh_h[0][k] = 0.0f;
    } else {
#pragma unroll
        for (int q = 0; q < DD / 2; q++) {
            w[q]      = pack2(Wi[(2 * q) * GG + p],          Wi[(2 * q + 1) * GG + p]);
            w[10 + q] = pack2(Wi[(2 * q) * GG + HH + p],     Wi[(2 * q + 1) * GG + HH + p]);
            w[20 + q] = pack2(Wi[(2 * q) * GG + 2 * HH + p], Wi[(2 * q + 1) * GG + 2 * HH + p]);
        }
#pragma unroll
        for (int q = DD / 2 + 20; q < 32; q++) w[q] = 0ull;
        b0 = bi[p]; b1 = bi[HH + p]; b2 = bi[2 * HH + p];
    }

    // x loaders: producers 0..19 own one input feature each
    const float* src = 0;
    float xa = 0.0f, xb = 0.0f;
    if (!proj && p < DD) {
        src = (p < NO_) ? (Yi + (size_t)n * TT * NO_ + p)
                        : (Xh + (size_t)n * TT * NS_ + (p - NO_));
        sh_x[0][p] = src[0];                 // x(0)
        sh_x[1][p] = src[NS_];               // x(1)  (stride NO_==NS_==10)
        xa = src[2 * NS_];                   // x(2)
        xb = src[3 * NS_];                   // x(3)
    }
    __syncthreads();

    // producers: xp(0) into ring slot 0
    if (!proj) {
        const ull* x2 = (const ull*)sh_x[0];
        ull cr = pack2(b0, 0.0f), cz = pack2(b1, 0.0f), cn = pack2(b2, 0.0f);
#pragma unroll
        for (int q = 0; q < DD / 2; q++) {
            cr = fma2(x2[q], w[q],      cr);
            cz = fma2(x2[q], w[10 + q], cz);
            cn = fma2(x2[q], w[20 + q], cn);
        }
        float2 f;
        f = unpack2(cr); sh_xp[0][p]          = f.x + f.y;
        f = unpack2(cz); sh_xp[0][HH + p]     = f.x + f.y;
        f = unpack2(cn); sh_xp[0][2 * HH + p] = f.x + f.y;
    }

    float* hs = g_hs + (size_t)n * TT * HH;

    for (int t = 0; t < TT; t++) {
        const int slot = t & 1;
        __syncthreads();   // sh_h[slot], sh_xp[slot], sh_x staged

        if (proj) {
            // ---- h-projection for gate column k (32 fma2, 4 chains) ----
            const ulonglong2* h4 = (const ulonglong2*)sh_h[slot];
            ull a0 = pack2(b0, 0.0f), a1 = 0ull, a2 = 0ull, a3 = 0ull;
#pragma unroll
            for (int q = 0; q < HH / 4; q += 2) {
                const ulonglong2 hva = h4[q];
                const ulonglong2 hvb = h4[q + 1];
                a0 = fma2(hva.x, w[2 * q],     a0);
                a1 = fma2(hva.y, w[2 * q + 1], a1);
                a2 = fma2(hvb.x, w[2 * q + 2], a2);
                a3 = fma2(hvb.y, w[2 * q + 3], a3);
            }
            const float2 f = unpack2(add2(add2(a0, a1), add2(a2, a3)));
            const float ah = f.x + f.y;                   // h@Wh_col + bh

            sh_g[k] = sh_xp[slot][k] + ah;
            if (k >= 2 * HH) sh_hn[k - 2 * HH] = ah;

            if (k < HH) {
                BAR_SYNC_1();
                const float r  = sigmoid_fast(sh_g[k]);
                const float z  = sigmoid_fast(sh_g[HH + k]);
                const float hn = sh_hn[k];
                // xn + r*hn = (xn + hn) + (r-1)*hn
                const float nn = tanh_fast(fmaf(r - 1.0f, hn, sh_g[2 * HH + k]));
                const float hnew = fmaf(z, hprev - nn, nn);   // (1-z)n + z h
                hprev = hnew;
                sh_h[slot ^ 1][k] = hnew;
                hs[(size_t)t * HH + k] = hnew;
            } else {
                BAR_ARRIVE_1();
            }
        } else {
            // ---- produce xp(t+1) into the other ring slot (off chain) ----
            if (t + 1 < TT) {
                const ull* x2 = (const ull*)sh_x[slot ^ 1];
                ull cr = pack2(b0, 0.0f), cz = pack2(b1, 0.0f), cn = pack2(b2, 0.0f);
#pragma unroll
                for (int q = 0; q < DD / 2; q++) {
                    cr = fma2(x2[q], w[q],      cr);
                    cz = fma2(x2[q], w[10 + q], cz);
                    cn = fma2(x2[q], w[20 + q], cn);
                }
                float2 f;
                f = unpack2(cr); sh_xp[slot ^ 1][p]          = f.x + f.y;
                f = unpack2(cz); sh_xp[slot ^ 1][HH + p]     = f.x + f.y;
                f = unpack2(cn); sh_xp[slot ^ 1][2 * HH + p] = f.x + f.y;
            }
            if (p < DD) {
                if (t + 2 < TT) sh_x[slot][p] = xa;        // stage x(t+2)
                xa = xb;
                if (t + 4 < TT) xb = src[(size_t)(t + 4) * NS_];
            }
        }
    }
}

// ---------------------------------------------------------------------------
// Likelihood: one thread per (n,t), 128-thread blocks. Heads computed in two
// staged passes (vr then mu) to cut peak register pressure; packed Cholesky.
// Last block writes the final scalar.
// ---------------------------------------------------------------------------
__global__ void __launch_bounds__(128) lik_kernel(
    const float* __restrict__ Yi, const float* __restrict__ Cw,
    const float* __restrict__ Hm, const float* __restrict__ mu_w,
    const float* __restrict__ W_mu, const float* __restrict__ b_mu,
    const float* __restrict__ W_var, const float* __restrict__ b_var,
    float* __restrict__ out)
{
    __shared__ ull sWm2[(HH / 2) * NS_];
    __shared__ ull sWv2[(HH / 2) * NS_];
    __shared__ float sH[NO_ * NS_], sbm[NS_], sbv[NS_], smw[NO_];
    __shared__ double wsum[4];

    const int tid = threadIdx.x;
    for (int i = tid; i < (HH / 2) * NS_; i += 128) {
        const int p = i / NS_, j = i - p * NS_;
        sWm2[i] = pack2(W_mu[(2 * p) * NS_ + j],  W_mu[(2 * p + 1) * NS_ + j]);
        sWv2[i] = pack2(W_var[(2 * p) * NS_ + j], W_var[(2 * p + 1) * NS_ + j]);
    }
    if (tid < NO_ * NS_) sH[tid] = Hm[tid];
    if (tid < NS_) { sbm[tid] = b_mu[tid]; sbv[tid] = b_var[tid]; }
    if (tid < NO_) smw[tid] = mu_w[tid];
    __syncthreads();

    const int idx = blockIdx.x * 128 + tid;      // grid exact: NN*TT/128
    const int n = idx / TT;
    const ulonglong2* h4 = (const ulonglong2*)(g_hs + (size_t)idx * HH);

    // ---- pass 1: vr head -> var (softplus) ----
    float var[NS_];
    {
        ull vr2[NS_];
#pragma unroll
        for (int j = 0; j < NS_; j++) vr2[j] = 0ull;
#pragma unroll
        for (int q = 0; q < HH / 4; q++) {
            const ulonglong2 hv = h4[q];
            const int p0 = 2 * q;
#pragma unroll
            for (int j = 0; j < NS_; j++) vr2[j] = fma2(hv.x, sWv2[p0 * NS_ + j], vr2[j]);
#pragma unroll
            for (int j = 0; j < NS_; j++) vr2[j] = fma2(hv.y, sWv2[(p0 + 1) * NS_ + j], vr2[j]);
        }
#pragma unroll
        for (int j = 0; j < NS_; j++) {
            const float2 v = unpack2(vr2[j]);
            const float x = sbv[j] + v.x + v.y;
            var[j] = (x > 15.0f) ? x : __logf(1.0f + __expf(x));
        }
    }

    // ---- pass 2: mu head -> residual e ----
    float e[NO_];
    {
        ull mu2[NS_];
#pragma unroll
        for (int j = 0; j < NS_; j++) mu2[j] = 0ull;
#pragma unroll
        for (int q = 0; q < HH / 4; q++) {
            const ulonglong2 hv = h4[q];
            const int p0 = 2 * q;
#pragma unroll
            for (int j = 0; j < NS_; j++) mu2[j] = fma2(hv.x, sWm2[p0 * NS_ + j], mu2[j]);
#pragma unroll
            for (int j = 0; j < NS_; j++) mu2[j] = fma2(hv.y, sWm2[(p0 + 1) * NS_ + j], mu2[j]);
        }
        float mu[NS_];
#pragma unroll
        for (int j = 0; j < NS_; j++) {
            const float2 m = unpack2(mu2[j]);
            mu[j] = sbm[j] + m.x + m.y;
        }
#pragma unroll
        for (int i = 0; i < NO_; i++) {
            float m = smw[i];
#pragma unroll
            for (int j = 0; j < NS_; j++) m = fmaf(sH[i * NS_ + j], mu[j], m);
            e[i] = Yi[(size_t)idx * NO_ + i] - m;
        }
    }

    // A = H diag(var) H^T + Cw, packed lower triangle
    float A[NO_ * (NO_ + 1) / 2];
    const float* cw = Cw + (size_t)n * NO_ * NO_;
#pragma unroll
    for (int i = 0; i < NO_; i++)
#pragma unroll
        for (int kk = 0; kk <= i; kk++)
            A[i * (i + 1) / 2 + kk] = cw[i * NO_ + kk];
#pragma unroll
    for (int j = 0; j < NS_; j++) {
        const float vj = var[j];
        float hj[NO_];
#pragma unroll
        for (int i = 0; i < NO_; i++) hj[i] = sH[i * NS_ + j];
#pragma unroll
        for (int i = 0; i < NO_; i++) {
            const float hv = hj[i] * vj;
#pragma unroll
            for (int kk = 0; kk <= i; kk++)
                A[i * (i + 1) / 2 + kk] = fmaf(hv, hj[kk], A[i * (i + 1) / 2 + kk]);
        }
    }

    // in-place packed Cholesky; logdet = sum log(s_i) since Lii^2 = s_i
    float rdi[NO_];
    float logdet = 0.0f;
#pragma unroll
    for (int i = 0; i < NO_; i++) {
#pragma unroll
        for (int kk = 0; kk < i; kk++) {
            float s = A[i * (i + 1) / 2 + kk];
#pragma unroll
            for (int j2 = 0; j2 < NO_; j2++)
                if (j2 < kk)
                    s -= A[i * (i + 1) / 2 + j2] * A[kk * (kk + 1) / 2 + j2];
            A[i * (i + 1) / 2 + kk] = s * rdi[kk];
        }
        float s = A[i * (i + 1) / 2 + i];
#pragma unroll
        for (int j2 = 0; j2 < NO_; j2++)
            if (j2 < i) {
                const float l = A[i * (i + 1) / 2 + j2];
                s -= l * l;
            }
        rdi[i] = rsqrtf(s);
        logdet += __logf(s);
    }

    // forward solve z = L^{-1} e ; quad = |z|^2
    float quad = 0.0f;
    float zv[NO_];
#pragma unroll
    for (int i = 0; i < NO_; i++) {
        float s = e[i];
#pragma unroll
        for (int j2 = 0; j2 < NO_; j2++)
            if (j2 < i) s -= A[i * (i + 1) / 2 + j2] * zv[j2];
        zv[i] = s * rdi[i];
        quad = fmaf(zv[i], zv[i], quad);
    }

    double local = (double)(logdet + quad);

    // block reduction -> one atomicAdd; last block finalizes
    for (int off = 16; off > 0; off >>= 1)
        local += __shfl_down_sync(0xffffffffu, local, off);
    if ((tid & 31) == 0) wsum[tid >> 5] = local;
    __syncthreads();
    if (tid == 0) {
        double s = wsum[0] + wsum[1] + wsum[2] + wsum[3];
        atomicAdd(&g_acc, s);
        __threadfence();
        const unsigned int d = atomicAdd(&g_done, 1u);
        if (d == gridDim.x - 1) {
            __threadfence();
            const double LOG2PI = 1.8378770664093453;
            const double acc = *((volatile double*)&g_acc);
            out[0] = (float)(-0.5 * LOG2PI - 0.5 * acc / ((double)NN * TT * NO_));
        }
    }
}

extern "C" void kernel_launch(void* const* d_in, const int* in_sizes, int n_in,
                              void* d_out, int out_size)
{
    const float* Yi    = (const float*)d_in[0];
    const float* Xh    = (const float*)d_in[1];
    const float* Cw    = (const float*)d_in[2];
    const float* Hm    = (const float*)d_in[3];
    const float* mu_w  = (const float*)d_in[4];
    const float* Wi    = (const float*)d_in[5];
    const float* Wh    = (const float*)d_in[6];
    const float* bi    = (const float*)d_in[7];
    const float* bh    = (const float*)d_in[8];
    const float* W_mu  = (const float*)d_in[9];
    const float* b_mu  = (const float*)d_in[10];
    const float* W_var = (const float*)d_in[11];
    const float* b_var = (const float*)d_in[12];
    float* out = (float*)d_out;

    gru_scan_kernel<<<NN, 256>>>(Yi, Xh, Wi, Wh, bi, bh);
    lik_kernel<<<NN * TT / 128, 128>>>(Yi, Cw, Hm, mu_w, W_mu, b_mu, W_var, b_var, out);
}